// round 3
// baseline (speedup 1.0000x reference)
#include <cuda_runtime.h>

// GatedHippoCell scan: B=128, T=512, N=512.
// Strategy: persistent cooperative kernel, 128 blocks (all co-resident on 148 SMs),
// one custom grid barrier per timestep. State c is kept lazily factored as
// c_t = CAraw_t + f_t * B_t so only ONE global sync per step is needed.
// h_{t} is written straight into d_out (hs) and re-read next step.

#define BATCH 128
#define TLEN 512
#define NH 512
#define NW (NH + 1)
#define GRID_X 128
#define NTHR 256
#define BT 32   // batch tile per block  (grid = 4 b-groups x 32 n-groups)
#define NT 16   // n tile per block
#define KC 64   // k chunk staged in smem
#define NCH (NH / KC)

// Scratch state (device globals: no allocations allowed)
__device__ float g_CA[2][BATCH][NH];   // CAraw double buffer
__device__ float g_F[3][BATCH];        // f_t triple buffer (atomic accumulated)
__device__ unsigned int g_bar;         // monotonic grid barrier counter

__global__ void hippo_init() {
    int t = threadIdx.x;
    if (t == 0) g_bar = 0u;
    if (t < 3 * BATCH) ((float*)g_F)[t] = 0.0f;
}

__device__ __forceinline__ void grid_barrier(unsigned target) {
    __syncthreads();
    if (threadIdx.x == 0) {
        __threadfence();                 // release all prior writes (cumulative via syncthreads)
        atomicAdd(&g_bar, 1u);
        volatile unsigned* p = &g_bar;
        while (*p < target) { __nanosleep(64); }
        __threadfence();                 // acquire
    }
    __syncthreads();
}

__global__ void __launch_bounds__(NTHR, 1) hippo_main(
    const float* __restrict__ x,
    const float* __restrict__ Wi, const float* __restrict__ bi,
    const float* __restrict__ Wh, const float* __restrict__ bh,
    const float* __restrict__ Wf, const float* __restrict__ bf,
    const float* __restrict__ Ast, const float* __restrict__ Bst,
    float* __restrict__ out, int write_cf)
{
    // smem: k-major padded tiles, unioned with the cross-warp reduction buffer.
    // tiles: CS[64][33] + HS[64][33] + WI/WH/AA[64][17] = 7488 floats
    // RED:   [512 outputs][17 slots(8 gate + 8 ca)]     = 8704 floats  -> max 8704
    __shared__ float smem[8704];
    float* CS  = smem;                 // c (reconstructed) [kk][bb], stride 33
    float* HSm = smem + KC * 33;       // h_prev            [kk][bb], stride 33
    float* WIs = smem + 2 * KC * 33;   // Wi' rows          [kk][nn], stride 17
    float* WHs = WIs + KC * 17;
    float* AAs = WHs + KC * 17;
    float* RED = smem;                 // reduction buffer (reused after compute)

    const int tid  = threadIdx.x;
    const int wid  = tid >> 5;
    const int lane = tid & 31;
    const int lb   = lane & 7;         // lane's b sub-index (4 regs: lb+8r)
    const int lnn  = lane >> 3;        // lane's n sub-index (4 regs: lnn+4r)
    const int bg = blockIdx.x & 3, ng = blockIdx.x >> 2;
    const int b0 = bg * BT, n0 = ng * NT;

    const int ldb = tid >> 4;          // loader row 0..15 (b and b+16 / n)
    const int ldk = (tid & 15) * 4;    // loader k offset within chunk

    const int eb  = tid >> 3;          // epilogue local b 0..31
    const int en  = (tid & 7) * 2;     // epilogue local n pair base
    const int bG  = b0 + eb;
    const int nG0 = n0 + en, nG1 = nG0 + 1;

    unsigned target = 0;

    for (int i = 0; i < TLEN; ++i) {
        const int cur = i & 1, prv = cur ^ 1;
        const float* __restrict__ Ar = Ast + (size_t)i * NH * NH;
        const float* Bp = Bst + (size_t)(i - 1) * NH;   // only deref'd when i>0
        const float* Fp = g_F[(i + 2) % 3];             // f_{i-1}
        float*       Fc = g_F[i % 3];                   // f_i (accumulated now)

        // zero the buffer f_{i+1} will use (its last reader finished at barrier i-1)
        if (blockIdx.x == 0 && tid < BATCH) g_F[(i + 1) % 3][tid] = 0.0f;

        float accg[4][4], accc[4][4];
        #pragma unroll
        for (int a = 0; a < 4; ++a)
            #pragma unroll
            for (int b = 0; b < 4; ++b) { accg[a][b] = 0.f; accc[a][b] = 0.f; }

        if (i > 0) {
            const float fA  = Fp[b0 + ldb];
            const float fBv = Fp[b0 + ldb + 16];
            const float* caP0 = &g_CA[prv][b0 + ldb][0];
            const float* hP0  = out + ((size_t)(b0 + ldb) * TLEN + (i - 1)) * NH;
            const float* wiP0 = Wi + (size_t)(n0 + ldb) * NW + 1;
            const float* whP0 = Wh + (size_t)(n0 + ldb) * NW + 1;
            const float* aP0  = Ar + (size_t)(n0 + ldb) * NH;

            float4 c0v, c1v, h0v, h1v, a4;
            float wi0, wi1, wi2, wi3, wh0, wh1, wh2, wh3;

            // prefetch chunk 0 into registers
            {
                const int k = ldk;
                float4 b4 = *(const float4*)&Bp[k];
                c0v = *(const float4*)&caP0[k];
                c1v = *(const float4*)&caP0[k + 16 * NH];
                c0v.x += fA * b4.x;  c0v.y += fA * b4.y;  c0v.z += fA * b4.z;  c0v.w += fA * b4.w;
                c1v.x += fBv * b4.x; c1v.y += fBv * b4.y; c1v.z += fBv * b4.z; c1v.w += fBv * b4.w;
                h0v = *(const float4*)&hP0[k];
                h1v = *(const float4*)&hP0[k + (size_t)16 * TLEN * NH];
                wi0 = wiP0[k]; wi1 = wiP0[k + 1]; wi2 = wiP0[k + 2]; wi3 = wiP0[k + 3];
                wh0 = whP0[k]; wh1 = whP0[k + 1]; wh2 = whP0[k + 2]; wh3 = whP0[k + 3];
                a4 = *(const float4*)&aP0[k];
            }

            for (int ch = 0; ch < NCH; ++ch) {
                // stage registers -> smem (conflict-free: odd strides)
                CS [(ldk + 0) * 33 + ldb]      = c0v.x;
                CS [(ldk + 1) * 33 + ldb]      = c0v.y;
                CS [(ldk + 2) * 33 + ldb]      = c0v.z;
                CS [(ldk + 3) * 33 + ldb]      = c0v.w;
                CS [(ldk + 0) * 33 + ldb + 16] = c1v.x;
                CS [(ldk + 1) * 33 + ldb + 16] = c1v.y;
                CS [(ldk + 2) * 33 + ldb + 16] = c1v.z;
                CS [(ldk + 3) * 33 + ldb + 16] = c1v.w;
                HSm[(ldk + 0) * 33 + ldb]      = h0v.x;
                HSm[(ldk + 1) * 33 + ldb]      = h0v.y;
                HSm[(ldk + 2) * 33 + ldb]      = h0v.z;
                HSm[(ldk + 3) * 33 + ldb]      = h0v.w;
                HSm[(ldk + 0) * 33 + ldb + 16] = h1v.x;
                HSm[(ldk + 1) * 33 + ldb + 16] = h1v.y;
                HSm[(ldk + 2) * 33 + ldb + 16] = h1v.z;
                HSm[(ldk + 3) * 33 + ldb + 16] = h1v.w;
                WIs[(ldk + 0) * 17 + ldb] = wi0;
                WIs[(ldk + 1) * 17 + ldb] = wi1;
                WIs[(ldk + 2) * 17 + ldb] = wi2;
                WIs[(ldk + 3) * 17 + ldb] = wi3;
                WHs[(ldk + 0) * 17 + ldb] = wh0;
                WHs[(ldk + 1) * 17 + ldb] = wh1;
                WHs[(ldk + 2) * 17 + ldb] = wh2;
                WHs[(ldk + 3) * 17 + ldb] = wh3;
                AAs[(ldk + 0) * 17 + ldb] = a4.x;
                AAs[(ldk + 1) * 17 + ldb] = a4.y;
                AAs[(ldk + 2) * 17 + ldb] = a4.z;
                AAs[(ldk + 3) * 17 + ldb] = a4.w;
                __syncthreads();

                if (ch + 1 < NCH) {   // prefetch next chunk while computing this one
                    const int k = (ch + 1) * KC + ldk;
                    float4 b4 = *(const float4*)&Bp[k];
                    c0v = *(const float4*)&caP0[k];
                    c1v = *(const float4*)&caP0[k + 16 * NH];
                    c0v.x += fA * b4.x;  c0v.y += fA * b4.y;  c0v.z += fA * b4.z;  c0v.w += fA * b4.w;
                    c1v.x += fBv * b4.x; c1v.y += fBv * b4.y; c1v.z += fBv * b4.z; c1v.w += fBv * b4.w;
                    h0v = *(const float4*)&hP0[k];
                    h1v = *(const float4*)&hP0[k + (size_t)16 * TLEN * NH];
                    wi0 = wiP0[k]; wi1 = wiP0[k + 1]; wi2 = wiP0[k + 2]; wi3 = wiP0[k + 3];
                    wh0 = whP0[k]; wh1 = whP0[k + 1]; wh2 = whP0[k + 2]; wh3 = whP0[k + 3];
                    a4 = *(const float4*)&aP0[k];
                }

                // split-K compute: warp w handles kk in [w*8, w*8+8) of this chunk,
                // over ALL 32b x 16n outputs (4x4 register tile per lane)
                const int kb = wid << 3;
                #pragma unroll
                for (int k8 = 0; k8 < 8; ++k8) {
                    const float* csr = CS  + (kb + k8) * 33;
                    const float* hsr = HSm + (kb + k8) * 33;
                    const float* wir = WIs + (kb + k8) * 17;
                    const float* whr = WHs + (kb + k8) * 17;
                    const float* aar = AAs + (kb + k8) * 17;
                    float cv[4], hv[4], wv[4], uv[4], av[4];
                    #pragma unroll
                    for (int r = 0; r < 4; ++r) {
                        cv[r] = csr[lb + 8 * r];
                        hv[r] = hsr[lb + 8 * r];
                        wv[r] = wir[lnn + 4 * r];
                        uv[r] = whr[lnn + 4 * r];
                        av[r] = aar[lnn + 4 * r];
                    }
                    #pragma unroll
                    for (int rb = 0; rb < 4; ++rb)
                        #pragma unroll
                        for (int rn = 0; rn < 4; ++rn) {
                            accg[rb][rn] = fmaf(cv[rb], wv[rn], accg[rb][rn]);
                            accg[rb][rn] = fmaf(hv[rb], uv[rn], accg[rb][rn]);
                            accc[rb][rn] = fmaf(cv[rb], av[rn], accc[rb][rn]);
                        }
                }
                __syncthreads();
            }

            // cross-warp (split-K) reduction staging
            #pragma unroll
            for (int rb = 0; rb < 4; ++rb)
                #pragma unroll
                for (int rn = 0; rn < 4; ++rn) {
                    const int o = ((lb + 8 * rb) * 16 + (lnn + 4 * rn)) * 17;
                    RED[o + wid]     = accg[rb][rn];
                    RED[o + 8 + wid] = accc[rb][rn];
                }
            __syncthreads();
        }

        // ---- epilogue: each thread owns outputs (eb, en) and (eb, en+1) ----
        float g0 = 0.f, g1 = 0.f, ca0 = 0.f, ca1 = 0.f;
        if (i > 0) {
            const int o0 = (eb * 16 + en) * 17, o1 = o0 + 17;
            #pragma unroll
            for (int w = 0; w < 8; ++w) {
                g0  += RED[o0 + w];  ca0 += RED[o0 + 8 + w];
                g1  += RED[o1 + w];  ca1 += RED[o1 + 8 + w];
            }
        }
        const float xv  = x[bG * TLEN + i];
        const float wx0 = Wi[(size_t)nG0 * NW] + Wh[(size_t)nG0 * NW];
        const float wx1 = Wi[(size_t)nG1 * NW] + Wh[(size_t)nG1 * NW];
        const float gate0 = g0 + xv * wx0 + bi[nG0] + bh[nG0];
        const float gate1 = g1 + xv * wx1 + bi[nG1] + bh[nG1];
        const float o0s = 1.0f / (1.0f + __expf(-gate0));
        const float o1s = 1.0f / (1.0f + __expf(-gate1));
        float cp0 = 0.f, cp1 = 0.f;
        if (i > 0) {
            const float fpb = Fp[bG];
            cp0 = g_CA[prv][bG][nG0] + fpb * Bp[nG0];
            cp1 = g_CA[prv][bG][nG1] + fpb * Bp[nG1];
        }
        const float h0 = o0s * tanhf(cp0);
        const float h1 = o1s * tanhf(cp1);
        float* orow = out + ((size_t)bG * TLEN + i) * NH;
        orow[nG0] = h0;
        orow[nG1] = h1;
        g_CA[cur][bG][nG0] = ca0;
        g_CA[cur][bG][nG1] = ca1;

        // f_i partial: reduce h_new . Wf' over this block's 16 n (8 lanes x 2)
        float fp = fmaf(h0, Wf[1 + nG0], h1 * Wf[1 + nG1]);
        fp += __shfl_xor_sync(0xffffffffu, fp, 1);
        fp += __shfl_xor_sync(0xffffffffu, fp, 2);
        fp += __shfl_xor_sync(0xffffffffu, fp, 4);
        if ((tid & 7) == 0) {
            float add = fp;
            if (ng == 0) add = fmaf(xv, Wf[0], add + bf[0]);   // bias term exactly once per b
            atomicAdd(&Fc[bG], add);
        }

        target += GRID_X;
        grid_barrier(target);
    }

    // final c_T = CAraw_T + f_T * B_T  (f_T complete after last barrier)
    if (write_cf) {
        const float* Ff = g_F[(TLEN - 1) % 3];
        const float* Bl = Bst + (size_t)(TLEN - 1) * NH;
        const int last = (TLEN - 1) & 1;
        float* cf = out + (size_t)BATCH * TLEN * NH;
        const float fb = Ff[bG];
        cf[(size_t)bG * NH + nG0] = g_CA[last][bG][nG0] + fb * Bl[nG0];
        cf[(size_t)bG * NH + nG1] = g_CA[last][bG][nG1] + fb * Bl[nG1];
    }
}

extern "C" void kernel_launch(void* const* d_in, const int* in_sizes, int n_in,
                              void* d_out, int out_size) {
    // metadata order: x, h0, c0, Wi, bi, Wh, bh, Wf, bf, A_stack, B_stack
    const float* x   = (const float*)d_in[0];
    const float* Wi  = (const float*)d_in[3];
    const float* bi  = (const float*)d_in[4];
    const float* Wh  = (const float*)d_in[5];
    const float* bh  = (const float*)d_in[6];
    const float* Wf  = (const float*)d_in[7];
    const float* bf  = (const float*)d_in[8];
    const float* Ast = (const float*)d_in[9];
    const float* Bst = (const float*)d_in[10];
    float* out = (float*)d_out;

    const long long hs_elems = (long long)BATCH * TLEN * NH;
    const int write_cf = ((long long)out_size >= hs_elems + (long long)BATCH * NH) ? 1 : 0;

    hippo_init<<<1, 512>>>();
    hippo_main<<<GRID_X, NTHR>>>(x, Wi, bi, Wh, bh, Wf, bf, Ast, Bst, out, write_cf);
}

// round 9
// speedup vs baseline: 1.0874x; 1.0874x over previous
#include <cuda_runtime.h>

// GatedHippoCell scan: B=128, T=512, N=512.
// Persistent cooperative kernel, 128 blocks (all co-resident on 148 SMs, 1 CTA/SM),
// one custom grid barrier per timestep. State c is kept lazily factored as
// c_t = CAraw_t + f_t * B_t so only ONE global sync per step is needed.
// h_t is written straight into d_out (hs) and re-read next step.
// R4 changes: Wi/Wh persistent in smem (loaded once), pre-barrier A/B prefetch,
// invariant epilogue scalars hoisted, clock-bounded barrier (no device wedge).

#define BATCH 128
#define TLEN 512
#define NH 512
#define NW (NH + 1)
#define GRID_X 128
#define NTHR 256
#define BT 32   // batch tile per block  (grid = 4 b-groups x 32 n-groups)
#define NT 16   // n tile per block
#define KC 64   // k chunk staged in smem
#define NCH (NH / KC)

// smem layout (floats), dynamic:
//  [0,2112)        CS   staging c        [kk][bb] stride 33
//  [2112,4224)     HS   staging h_prev   [kk][bb] stride 33
//  [4224,5312)     AA   staging A rows   [kk][nn] stride 17
//  [5312,14016)    RED  split-K reduction [512 outputs][17]
//  [14016,22720)   WIp  persistent Wi'   [k=0..511][nn] stride 17
//  [22720,31424)   WHp  persistent Wh'   [k=0..511][nn] stride 17
#define SMEM_FLOATS 31424
#define SMEM_BYTES (SMEM_FLOATS * 4)

// Scratch state (device globals: no allocations allowed)
__device__ float g_CA[2][BATCH][NH];   // CAraw double buffer
__device__ float g_F[3][BATCH];        // f_t triple buffer (atomic accumulated)
__device__ unsigned int g_bar;         // monotonic grid barrier counter

__global__ void hippo_init() {
    int t = threadIdx.x;
    if (t == 0) g_bar = 0u;
    if (t < 3 * BATCH) ((float*)g_F)[t] = 0.0f;
}

__device__ __forceinline__ void grid_barrier(unsigned target) {
    __syncthreads();
    if (threadIdx.x == 0) {
        __threadfence();                 // release (cumulative: block's writes visible gpu-wide)
        atomicAdd(&g_bar, 1u);
        volatile unsigned* p = &g_bar;
        if (*p < target) {
            long long t0 = clock64();
            while (*p < target) {
                __nanosleep(32);
                // safety valve: never wedge the device. ~0.2s @ ~2GHz.
                if (clock64() - t0 > 400000000LL) break;
            }
        }
        __threadfence();                 // acquire
    }
    __syncthreads();
}

__global__ void __launch_bounds__(NTHR, 1) hippo_main(
    const float* __restrict__ x,
    const float* __restrict__ Wi, const float* __restrict__ bi,
    const float* __restrict__ Wh, const float* __restrict__ bh,
    const float* __restrict__ Wf, const float* __restrict__ bf,
    const float* __restrict__ Ast, const float* __restrict__ Bst,
    float* __restrict__ out, int write_cf)
{
    extern __shared__ float smem[];
    float* CS  = smem;                 // [kk][bb] stride 33
    float* HSm = smem + 2112;          // [kk][bb] stride 33
    float* AAs = smem + 4224;          // [kk][nn] stride 17
    float* RED = smem + 5312;          // [512][17]
    float* WIp = smem + 14016;         // [k][nn]  stride 17, persistent
    float* WHp = smem + 22720;         // [k][nn]  stride 17, persistent

    const int tid  = threadIdx.x;
    const int wid  = tid >> 5;
    const int lane = tid & 31;
    const int lb   = lane & 7;         // lane's b sub-index (4 regs: lb+8r)
    const int lnn  = lane >> 3;        // lane's n sub-index (4 regs: lnn+4r)
    const int bg = blockIdx.x & 3, ng = blockIdx.x >> 2;
    const int b0 = bg * BT, n0 = ng * NT;

    const int ldb = tid >> 4;          // loader row 0..15 (b and b+16 / n)
    const int ldk = (tid & 15) * 4;    // loader k offset within chunk

    const int eb  = tid >> 3;          // epilogue local b 0..31
    const int en  = (tid & 7) * 2;     // epilogue local n pair base
    const int bG  = b0 + eb;
    const int nG0 = n0 + en, nG1 = nG0 + 1;

    // ---- one-time: persistent Wi'/Wh' slices into smem (coalesced over k) ----
    for (int idx = tid; idx < NT * NH; idx += NTHR) {
        const int k  = idx & (NH - 1);
        const int nl = idx >> 9;           // 0..15
        WIp[k * 17 + nl] = Wi[(size_t)(n0 + nl) * NW + 1 + k];
        WHp[k * 17 + nl] = Wh[(size_t)(n0 + nl) * NW + 1 + k];
    }

    // ---- one-time: invariant epilogue scalars ----
    const float wx0   = Wi[(size_t)nG0 * NW] + Wh[(size_t)nG0 * NW];
    const float wx1   = Wi[(size_t)nG1 * NW] + Wh[(size_t)nG1 * NW];
    const float bsum0 = bi[nG0] + bh[nG0];
    const float bsum1 = bi[nG1] + bh[nG1];
    const float wf0   = Wf[1 + nG0];
    const float wf1   = Wf[1 + nG1];
    const float wfx   = Wf[0];
    const float bf0   = bf[0];
    __syncthreads();

    unsigned target = 0;
    // pre-barrier prefetch registers for next step's chunk 0 (input-only data)
    float4 a4_pf = make_float4(0.f, 0.f, 0.f, 0.f);
    float4 b4_pf = make_float4(0.f, 0.f, 0.f, 0.f);

    for (int i = 0; i < TLEN; ++i) {
        const int cur = i & 1, prv = cur ^ 1;
        const float* Bp = Bst + (size_t)(i - 1) * NH;   // only deref'd when i>0
        const float* Fp = g_F[(i + 2) % 3];             // f_{i-1}
        float*       Fc = g_F[i % 3];                   // f_i (accumulated now)

        // zero the buffer f_{i+1} will use (its last reader finished at barrier i-1)
        if (blockIdx.x == 0 && tid < BATCH) g_F[(i + 1) % 3][tid] = 0.0f;

        float accg[4][4], accc[4][4];
        #pragma unroll
        for (int a = 0; a < 4; ++a)
            #pragma unroll
            for (int b = 0; b < 4; ++b) { accg[a][b] = 0.f; accc[a][b] = 0.f; }

        if (i > 0) {
            const float fA  = Fp[b0 + ldb];
            const float fBv = Fp[b0 + ldb + 16];
            const float* caP0 = &g_CA[prv][b0 + ldb][0];
            const float* hP0  = out + ((size_t)(b0 + ldb) * TLEN + (i - 1)) * NH;
            const float* aP0  = Ast + (size_t)i * NH * NH + (size_t)(n0 + ldb) * NH;

            float4 c0v, c1v, h0v, h1v, a4;

            // chunk 0: A/B already prefetched before the barrier; load c/h now
            {
                const int k = ldk;
                float4 b4 = b4_pf;
                a4 = a4_pf;
                c0v = *(const float4*)&caP0[k];
                c1v = *(const float4*)&caP0[k + 16 * NH];
                c0v.x += fA * b4.x;  c0v.y += fA * b4.y;  c0v.z += fA * b4.z;  c0v.w += fA * b4.w;
                c1v.x += fBv * b4.x; c1v.y += fBv * b4.y; c1v.z += fBv * b4.z; c1v.w += fBv * b4.w;
                h0v = *(const float4*)&hP0[k];
                h1v = *(const float4*)&hP0[k + (size_t)16 * TLEN * NH];
            }

            for (int ch = 0; ch < NCH; ++ch) {
                // stage registers -> smem (conflict-light: odd strides)
                CS [(ldk + 0) * 33 + ldb]      = c0v.x;
                CS [(ldk + 1) * 33 + ldb]      = c0v.y;
                CS [(ldk + 2) * 33 + ldb]      = c0v.z;
                CS [(ldk + 3) * 33 + ldb]      = c0v.w;
                CS [(ldk + 0) * 33 + ldb + 16] = c1v.x;
                CS [(ldk + 1) * 33 + ldb + 16] = c1v.y;
                CS [(ldk + 2) * 33 + ldb + 16] = c1v.z;
                CS [(ldk + 3) * 33 + ldb + 16] = c1v.w;
                HSm[(ldk + 0) * 33 + ldb]      = h0v.x;
                HSm[(ldk + 1) * 33 + ldb]      = h0v.y;
                HSm[(ldk + 2) * 33 + ldb]      = h0v.z;
                HSm[(ldk + 3) * 33 + ldb]      = h0v.w;
                HSm[(ldk + 0) * 33 + ldb + 16] = h1v.x;
                HSm[(ldk + 1) * 33 + ldb + 16] = h1v.y;
                HSm[(ldk + 2) * 33 + ldb + 16] = h1v.z;
                HSm[(ldk + 3) * 33 + ldb + 16] = h1v.w;
                AAs[(ldk + 0) * 17 + ldb] = a4.x;
                AAs[(ldk + 1) * 17 + ldb] = a4.y;
                AAs[(ldk + 2) * 17 + ldb] = a4.z;
                AAs[(ldk + 3) * 17 + ldb] = a4.w;
                __syncthreads();

                if (ch + 1 < NCH) {   // prefetch next chunk while computing this one
                    const int k = (ch + 1) * KC + ldk;
                    float4 b4 = *(const float4*)&Bp[k];
                    c0v = *(const float4*)&caP0[k];
                    c1v = *(const float4*)&caP0[k + 16 * NH];
                    c0v.x += fA * b4.x;  c0v.y += fA * b4.y;  c0v.z += fA * b4.z;  c0v.w += fA * b4.w;
                    c1v.x += fBv * b4.x; c1v.y += fBv * b4.y; c1v.z += fBv * b4.z; c1v.w += fBv * b4.w;
                    h0v = *(const float4*)&hP0[k];
                    h1v = *(const float4*)&hP0[k + (size_t)16 * TLEN * NH];
                    a4 = *(const float4*)&aP0[k];
                }

                // split-K compute: warp w handles kk in [w*8, w*8+8) of this chunk,
                // over ALL 32b x 16n outputs (4x4 register tile per lane)
                const int kb = wid << 3;
                const float* wbase = WIp + (ch * KC + kb) * 17;
                const float* ubase = WHp + (ch * KC + kb) * 17;
                #pragma unroll
                for (int k8 = 0; k8 < 8; ++k8) {
                    const float* csr = CS  + (kb + k8) * 33;
                    const float* hsr = HSm + (kb + k8) * 33;
                    const float* wir = wbase + k8 * 17;
                    const float* whr = ubase + k8 * 17;
                    const float* aar = AAs + (kb + k8) * 17;
                    float cv[4], hv[4], wv[4], uv[4], av[4];
                    #pragma unroll
                    for (int r = 0; r < 4; ++r) {
                        cv[r] = csr[lb + 8 * r];
                        hv[r] = hsr[lb + 8 * r];
                        wv[r] = wir[lnn + 4 * r];
                        uv[r] = whr[lnn + 4 * r];
                        av[r] = aar[lnn + 4 * r];
                    }
                    #pragma unroll
                    for (int rb = 0; rb < 4; ++rb)
                        #pragma unroll
                        for (int rn = 0; rn < 4; ++rn) {
                            accg[rb][rn] = fmaf(cv[rb], wv[rn], accg[rb][rn]);
                            accg[rb][rn] = fmaf(hv[rb], uv[rn], accg[rb][rn]);
                            accc[rb][rn] = fmaf(cv[rb], av[rn], accc[rb][rn]);
                        }
                }
                __syncthreads();
            }

            // cross-warp (split-K) reduction staging
            #pragma unroll
            for (int rb = 0; rb < 4; ++rb)
                #pragma unroll
                for (int rn = 0; rn < 4; ++rn) {
                    const int o = ((lb + 8 * rb) * 16 + (lnn + 4 * rn)) * 17;
                    RED[o + wid]     = accg[rb][rn];
                    RED[o + 8 + wid] = accc[rb][rn];
                }
            __syncthreads();
        }

        // ---- epilogue: each thread owns outputs (eb, en) and (eb, en+1) ----
        float g0 = 0.f, g1 = 0.f, ca0 = 0.f, ca1 = 0.f;
        if (i > 0) {
            const int o0 = (eb * 16 + en) * 17, o1 = o0 + 17;
            #pragma unroll
            for (int w = 0; w < 8; ++w) {
                g0  += RED[o0 + w];  ca0 += RED[o0 + 8 + w];
                g1  += RED[o1 + w];  ca1 += RED[o1 + 8 + w];
            }
        }
        const float xv = x[bG * TLEN + i];
        const float gate0 = g0 + xv * wx0 + bsum0;
        const float gate1 = g1 + xv * wx1 + bsum1;
        const float o0s = 1.0f / (1.0f + __expf(-gate0));
        const float o1s = 1.0f / (1.0f + __expf(-gate1));
        float cp0 = 0.f, cp1 = 0.f;
        if (i > 0) {
            const float fpb = Fp[bG];
            cp0 = g_CA[prv][bG][nG0] + fpb * Bp[nG0];
            cp1 = g_CA[prv][bG][nG1] + fpb * Bp[nG1];
        }
        const float h0 = o0s * tanhf(cp0);
        const float h1 = o1s * tanhf(cp1);
        float* orow = out + ((size_t)bG * TLEN + i) * NH;
        orow[nG0] = h0;
        orow[nG1] = h1;
        g_CA[cur][bG][nG0] = ca0;
        g_CA[cur][bG][nG1] = ca1;

        // f_i partial: reduce h_new . Wf' over this block's 16 n (8 lanes x 2)
        float fp = fmaf(h0, wf0, h1 * wf1);
        fp += __shfl_xor_sync(0xffffffffu, fp, 1);
        fp += __shfl_xor_sync(0xffffffffu, fp, 2);
        fp += __shfl_xor_sync(0xffffffffu, fp, 4);
        if ((tid & 7) == 0) {
            float add = fp;
            if (ng == 0) add = fmaf(xv, wfx, add + bf0);   // bias term exactly once per b
            atomicAdd(&Fc[bG], add);
        }

        // ---- pre-barrier prefetch of next step's input-only chunk-0 data ----
        if (i + 1 < TLEN) {
            const float* aN = Ast + (size_t)(i + 1) * NH * NH + (size_t)(n0 + ldb) * NH;
            a4_pf = *(const float4*)&aN[ldk];
            b4_pf = *(const float4*)&Bst[(size_t)i * NH + ldk];   // B for step i+1
        }

        target += GRID_X;
        grid_barrier(target);
    }

    // final c_T = CAraw_T + f_T * B_T  (f_T complete after last barrier)
    if (write_cf) {
        const float* Ff = g_F[(TLEN - 1) % 3];
        const float* Bl = Bst + (size_t)(TLEN - 1) * NH;
        const int last = (TLEN - 1) & 1;
        float* cf = out + (size_t)BATCH * TLEN * NH;
        const float fb = Ff[bG];
        cf[(size_t)bG * NH + nG0] = g_CA[last][bG][nG0] + fb * Bl[nG0];
        cf[(size_t)bG * NH + nG1] = g_CA[last][bG][nG1] + fb * Bl[nG1];
    }
}

extern "C" void kernel_launch(void* const* d_in, const int* in_sizes, int n_in,
                              void* d_out, int out_size) {
    // metadata order: x, h0, c0, Wi, bi, Wh, bh, Wf, bf, A_stack, B_stack
    const float* x   = (const float*)d_in[0];
    const float* Wi  = (const float*)d_in[3];
    const float* bi  = (const float*)d_in[4];
    const float* Wh  = (const float*)d_in[5];
    const float* bh  = (const float*)d_in[6];
    const float* Wf  = (const float*)d_in[7];
    const float* bf  = (const float*)d_in[8];
    const float* Ast = (const float*)d_in[9];
    const float* Bst = (const float*)d_in[10];
    float* out = (float*)d_out;

    const long long hs_elems = (long long)BATCH * TLEN * NH;
    const int write_cf = ((long long)out_size >= hs_elems + (long long)BATCH * NH) ? 1 : 0;

    cudaFuncSetAttribute(hippo_main, cudaFuncAttributeMaxDynamicSharedMemorySize, SMEM_BYTES);

    hippo_init<<<1, 512>>>();
    hippo_main<<<GRID_X, NTHR, SMEM_BYTES>>>(x, Wi, bi, Wh, bh, Wf, bf, Ast, Bst, out, write_cf);
}